// round 2
// baseline (speedup 1.0000x reference)
#include <cuda_runtime.h>
#include <math.h>

#define BB   8
#define LL   4096
#define DMD  256
#define DI   384
#define DS   8
#define CHUNK 32
#define MTOK (BB*LL)          // 32768 tokens
#define NCHUNK (MTOK/CHUNK)   // 1024

// ---------------- scratch (device globals; no allocation) ----------------
__device__ float g_xn[MTOK * DMD];        //  33.5 MB
__device__ float g_xz[MTOK * 3 * DI];     // 150.9 MB  cols: [0,384)=x_proj(silu) [384,768)=z(silu) [768,1152)=dt_in
__device__ float g_dt[MTOK * DI];         //  50.3 MB
__device__ float g_y [MTOK * DI];         //  50.3 MB

// ---------------- LayerNorm ----------------
__global__ void ln_kernel(const float* __restrict__ x,
                          const float* __restrict__ gamma,
                          const float* __restrict__ beta,
                          float* __restrict__ xn)
{
    int row = blockIdx.x;
    int t   = threadIdx.x;            // 256 threads, one per feature
    float v = x[(long)row * DMD + t];

    float s1 = v, s2 = v * v;
    #pragma unroll
    for (int o = 16; o; o >>= 1) {
        s1 += __shfl_xor_sync(0xffffffffu, s1, o);
        s2 += __shfl_xor_sync(0xffffffffu, s2, o);
    }
    __shared__ float red[16];
    int warp = t >> 5, lane = t & 31;
    if (lane == 0) { red[warp] = s1; red[8 + warp] = s2; }
    __syncthreads();
    if (t == 0) {
        float a = 0.f, b = 0.f;
        #pragma unroll
        for (int i = 0; i < 8; i++) { a += red[i]; b += red[8 + i]; }
        float mean = a * (1.0f / DMD);
        float var  = b * (1.0f / DMD) - mean * mean;
        red[0] = mean;
        red[8] = rsqrtf(var + 1e-5f);
    }
    __syncthreads();
    float mean = red[0], rstd = red[8];
    xn[(long)row * DMD + t] = (v - mean) * rstd * gamma[t] + beta[t];
}

// ---------------- SGEMM: C[M,N] = A[M,K] @ W[N,K]^T + bias, with epilogues ----------------
// EPI 0: silu for n < 2*DI, identity otherwise (GEMM1 -> xz)
// EPI 1: softplus                                 (GEMM2 -> dt)
// EPI 2: + resid[m*256+n]                         (GEMM3 -> out)
template <int EPI>
__global__ void __launch_bounds__(256)
sgemm(const float* __restrict__ A, int lda,
      const float* __restrict__ W, int ldb,
      const float* __restrict__ bias,
      float* __restrict__ C, int ldc,
      int K,
      const float* __restrict__ resid)
{
    __shared__ float As[8][128];
    __shared__ float Bs[8][128];

    int tid = threadIdx.x;
    int m0 = blockIdx.y * 128;
    int n0 = blockIdx.x * 128;
    int lr = tid >> 1;            // 0..127
    int lk = (tid & 1) * 4;       // 0 or 4

    const float* Aptr = A + (long)(m0 + lr) * lda + lk;
    const float* Wptr = W + (long)(n0 + lr) * ldb + lk;

    int tx = tid & 15, ty = tid >> 4;
    float acc[8][8];
    #pragma unroll
    for (int i = 0; i < 8; i++)
        #pragma unroll
        for (int j = 0; j < 8; j++) acc[i][j] = 0.f;

    for (int k0 = 0; k0 < K; k0 += 8) {
        float4 va = *(const float4*)(Aptr + k0);
        float4 vb = *(const float4*)(Wptr + k0);
        __syncthreads();
        As[lk + 0][lr] = va.x; As[lk + 1][lr] = va.y;
        As[lk + 2][lr] = va.z; As[lk + 3][lr] = va.w;
        Bs[lk + 0][lr] = vb.x; Bs[lk + 1][lr] = vb.y;
        Bs[lk + 2][lr] = vb.z; Bs[lk + 3][lr] = vb.w;
        __syncthreads();
        #pragma unroll
        for (int k = 0; k < 8; k++) {
            float ra[8], rb[8];
            *(float4*)(ra    ) = *(const float4*)&As[k][ty * 8];
            *(float4*)(ra + 4) = *(const float4*)&As[k][ty * 8 + 4];
            *(float4*)(rb    ) = *(const float4*)&Bs[k][tx * 8];
            *(float4*)(rb + 4) = *(const float4*)&Bs[k][tx * 8 + 4];
            #pragma unroll
            for (int i = 0; i < 8; i++)
                #pragma unroll
                for (int j = 0; j < 8; j++)
                    acc[i][j] = fmaf(ra[i], rb[j], acc[i][j]);
        }
    }

    #pragma unroll
    for (int i = 0; i < 8; i++) {
        int m = m0 + ty * 8 + i;
        #pragma unroll
        for (int jj = 0; jj < 8; jj += 4) {
            float4 o;
            float* op = &o.x;
            #pragma unroll
            for (int q = 0; q < 4; q++) {
                int n = n0 + tx * 8 + jj + q;
                float v = acc[i][jj + q] + bias[n];
                if (EPI == 0) {
                    if (n < 2 * DI) v = v / (1.f + __expf(-v));   // silu
                } else if (EPI == 1) {
                    v = fmaxf(v, 0.f) + log1pf(__expf(-fabsf(v))); // softplus
                } else if (EPI == 2) {
                    v += resid[(long)m * DMD + n];
                }
                op[q] = v;
            }
            *(float4*)&C[(long)m * ldc + n0 + tx * 8 + jj] = o;
        }
    }
}

// ---------------- chunked selective scan + gating ----------------
// One block per chunk (1024 blocks), 384 threads = one per channel di.
__global__ void __launch_bounds__(384)
scan_kernel(const float* __restrict__ xz,
            const float* __restrict__ dt,
            const float* __restrict__ A_log,
            const float* __restrict__ D_vec,
            float* __restrict__ y)
{
    __shared__ float a2[DI * DS];
    int tid = threadIdx.x;
    for (int i = tid; i < DI * DS; i += DI)
        a2[i] = -expf(A_log[i]) * 1.4426950408889634f;   // fold log2(e): exp(dt*A)=exp2(dt*a2)
    __syncthreads();

    int di = tid;
    float av[DS];
    #pragma unroll
    for (int s = 0; s < DS; s++) av[s] = a2[di * DS + s];
    float dval = D_vec[di];

    long row0 = (long)blockIdx.x * CHUNK;   // token index of chunk start
    float h[DS];
    #pragma unroll
    for (int s = 0; s < DS; s++) h[s] = 0.f;

    for (int t = 0; t < CHUNK; t++) {
        long m  = row0 + t;
        float dtv = dt[m * DI + di];
        float xv  = xz[m * (3 * DI) + di];         // silu(x_proj)
        float zv  = xz[m * (3 * DI) + DI + di];    // silu(z)
        float ys = 0.f;
        #pragma unroll
        for (int s = 0; s < DS; s++) {
            h[s] = fmaf(h[s], exp2f(dtv * av[s]), xv);
            ys += h[s];
        }
        y[m * DI + di] = fmaf(ys, zv, xv * dval);
    }
}

// ---------------- launch ----------------
extern "C" void kernel_launch(void* const* d_in, const int* in_sizes, int n_in,
                              void* d_out, int out_size)
{
    const float* x     = (const float*)d_in[0];
    const float* gamma = (const float*)d_in[1];
    const float* beta  = (const float*)d_in[2];
    const float* W_in  = (const float*)d_in[3];
    const float* b_in  = (const float*)d_in[4];
    const float* W_dt  = (const float*)d_in[5];
    const float* b_dt  = (const float*)d_in[6];
    const float* A_log = (const float*)d_in[7];
    const float* D_vec = (const float*)d_in[8];
    const float* W_out = (const float*)d_in[9];
    const float* b_out = (const float*)d_in[10];
    float* out = (float*)d_out;

    float *xn, *xz, *dtb, *yb;
    cudaGetSymbolAddress((void**)&xn,  g_xn);
    cudaGetSymbolAddress((void**)&xz,  g_xz);
    cudaGetSymbolAddress((void**)&dtb, g_dt);
    cudaGetSymbolAddress((void**)&yb,  g_y);

    // 1) LayerNorm
    ln_kernel<<<MTOK, DMD>>>(x, gamma, beta, xn);

    // 2) GEMM1: xz = xn @ W_in^T + b_in; silu on first 768 cols
    sgemm<0><<<dim3((3 * DI) / 128, MTOK / 128), 256>>>(
        xn, DMD, W_in, DMD, b_in, xz, 3 * DI, DMD, nullptr);

    // 3) GEMM2: dt = softplus(dt_in @ W_dt^T + b_dt)
    sgemm<1><<<dim3(DI / 128, MTOK / 128), 256>>>(
        xz + 2 * DI, 3 * DI, W_dt, DI, b_dt, dtb, DI, DI, nullptr);

    // 4) chunked scan + gating: y = scan(x_proj, dt) * z + x_proj * D
    scan_kernel<<<NCHUNK, DI>>>(xz, dtb, A_log, D_vec, yb);

    // 5) GEMM3: out = y @ W_out^T + b_out + residual
    sgemm<2><<<dim3(DMD / 128, MTOK / 128), 256>>>(
        yb, DI, W_out, DI, b_out, out, DMD, DI, x);
}

// round 3
// speedup vs baseline: 1.9986x; 1.9986x over previous
#include <cuda_runtime.h>
#include <cstdint>
#include <math.h>

#define BB   8
#define LL   4096
#define DMD  256
#define DI   384
#define DS   8
#define CHUNK 32
#define MTOK (BB*LL)          // 32768 tokens
#define NCHUNK (MTOK/CHUNK)   // 1024

// ---------------- scratch (device globals; no allocation) ----------------
__device__ float g_xn[MTOK * DMD];
__device__ float g_xz[MTOK * 3 * DI];   // [0,384)=silu(x_proj) [384,768)=silu(z) [768,1152)=dt_in
__device__ float g_dt[MTOK * DI];
__device__ float g_y [MTOK * DI];

// ---------------- LayerNorm ----------------
__global__ void ln_kernel(const float* __restrict__ x,
                          const float* __restrict__ gamma,
                          const float* __restrict__ beta,
                          float* __restrict__ xn)
{
    int row = blockIdx.x;
    int t   = threadIdx.x;
    float v = x[(long)row * DMD + t];

    float s1 = v, s2 = v * v;
    #pragma unroll
    for (int o = 16; o; o >>= 1) {
        s1 += __shfl_xor_sync(0xffffffffu, s1, o);
        s2 += __shfl_xor_sync(0xffffffffu, s2, o);
    }
    __shared__ float red[16];
    int warp = t >> 5, lane = t & 31;
    if (lane == 0) { red[warp] = s1; red[8 + warp] = s2; }
    __syncthreads();
    if (t == 0) {
        float a = 0.f, b = 0.f;
        #pragma unroll
        for (int i = 0; i < 8; i++) { a += red[i]; b += red[8 + i]; }
        float mean = a * (1.0f / DMD);
        float var  = b * (1.0f / DMD) - mean * mean;
        red[0] = mean;
        red[8] = rsqrtf(var + 1e-5f);
    }
    __syncthreads();
    float mean = red[0], rstd = red[8];
    xn[(long)row * DMD + t] = (v - mean) * rstd * gamma[t] + beta[t];
}

// ---------------- tf32 tensor-core GEMM ----------------
// C[M,N] = A[M,K] @ W[N,K]^T + bias (+epilogue). Row-major A/W (K contiguous).
// Block tile 128x128, K-tile 32, 8 warps (2 in M x 4 in N), warp tile 64x32.
// mma.sync.m16n8k8 tf32, fp32 accumulate. 2-stage cp.async pipeline.

#define KT32 32
#define SMPAD 36                       // 128 rows x 36 floats (padded)
#define STAGE_SZ (128 * SMPAD)         // floats per operand per stage

__device__ __forceinline__ uint32_t f2tf32(float f) {
    uint32_t u;
    asm volatile("cvt.rna.tf32.f32 %0, %1;\n" : "=r"(u) : "f"(f));
    return u;
}
__device__ __forceinline__ void cp16(void* s, const void* g) {
    uint32_t sa = (uint32_t)__cvta_generic_to_shared(s);
    asm volatile("cp.async.cg.shared.global [%0], [%1], 16;\n" :: "r"(sa), "l"(g));
}
__device__ __forceinline__ void cp_commit() {
    asm volatile("cp.async.commit_group;\n");
}

template <int EPI>
__global__ void __launch_bounds__(256)
mma_gemm(const float* __restrict__ A, int lda,
         const float* __restrict__ W, int ldb,
         const float* __restrict__ bias,
         float* __restrict__ C, int ldc,
         int K,
         const float* __restrict__ resid)
{
    extern __shared__ float sm[];
    float* As = sm;                    // [2][128][36]
    float* Bs = sm + 2 * STAGE_SZ;     // [2][128][36]

    int tid  = threadIdx.x;
    int warp = tid >> 5, lane = tid & 31;
    int wm = warp & 1, wn = warp >> 1;       // warp grid 2x4
    int gid = lane >> 2, tig = lane & 3;     // mma lane decomposition
    int m0 = blockIdx.y * 128, n0 = blockIdx.x * 128;

    // global load mapping: 256 thr -> 128 rows x 2 segments (16 floats each)
    int lrow = tid >> 1, lseg = (tid & 1) * 16;
    const float* Ag = A + (long)(m0 + lrow) * lda + lseg;
    const float* Wg = W + (long)(n0 + lrow) * ldb + lseg;
    float* as_dst = As + lrow * SMPAD + lseg;
    float* bs_dst = Bs + lrow * SMPAD + lseg;

    float acc[4][4][4];
    #pragma unroll
    for (int i = 0; i < 4; i++)
        #pragma unroll
        for (int j = 0; j < 4; j++)
            #pragma unroll
            for (int q = 0; q < 4; q++) acc[i][j][q] = 0.f;

    int KT = K / KT32;

    // prologue: stage 0
    {
        #pragma unroll
        for (int i = 0; i < 4; i++) {
            cp16(as_dst + i * 4, Ag + i * 4);
            cp16(bs_dst + i * 4, Wg + i * 4);
        }
        cp_commit();
    }

    for (int kt = 0; kt < KT; kt++) {
        if (kt + 1 < KT) {
            int s = (kt + 1) & 1;
            const float* a = Ag + (kt + 1) * KT32;
            const float* w = Wg + (kt + 1) * KT32;
            #pragma unroll
            for (int i = 0; i < 4; i++) {
                cp16(as_dst + s * STAGE_SZ + i * 4, a + i * 4);
                cp16(bs_dst + s * STAGE_SZ + i * 4, w + i * 4);
            }
            cp_commit();
            asm volatile("cp.async.wait_group 1;\n");
        } else {
            asm volatile("cp.async.wait_group 0;\n");
        }
        __syncthreads();

        int s = kt & 1;
        const float* as = As + s * STAGE_SZ;
        const float* bs = Bs + s * STAGE_SZ;

        #pragma unroll
        for (int k8 = 0; k8 < 4; k8++) {
            int kb = k8 * 8;
            uint32_t af[4][4], bf[4][2];
            #pragma unroll
            for (int ma = 0; ma < 4; ma++) {
                int r = wm * 64 + ma * 16 + gid;
                af[ma][0] = f2tf32(as[(long)r * SMPAD + kb + tig]);
                af[ma][1] = f2tf32(as[(long)(r + 8) * SMPAD + kb + tig]);
                af[ma][2] = f2tf32(as[(long)r * SMPAD + kb + tig + 4]);
                af[ma][3] = f2tf32(as[(long)(r + 8) * SMPAD + kb + tig + 4]);
            }
            #pragma unroll
            for (int na = 0; na < 4; na++) {
                int c = wn * 32 + na * 8 + gid;
                bf[na][0] = f2tf32(bs[(long)c * SMPAD + kb + tig]);
                bf[na][1] = f2tf32(bs[(long)c * SMPAD + kb + tig + 4]);
            }
            #pragma unroll
            for (int ma = 0; ma < 4; ma++)
                #pragma unroll
                for (int na = 0; na < 4; na++) {
                    asm volatile(
                        "mma.sync.aligned.m16n8k8.row.col.f32.tf32.tf32.f32 "
                        "{%0,%1,%2,%3}, {%4,%5,%6,%7}, {%8,%9}, {%0,%1,%2,%3};\n"
                        : "+f"(acc[ma][na][0]), "+f"(acc[ma][na][1]),
                          "+f"(acc[ma][na][2]), "+f"(acc[ma][na][3])
                        : "r"(af[ma][0]), "r"(af[ma][1]), "r"(af[ma][2]), "r"(af[ma][3]),
                          "r"(bf[na][0]), "r"(bf[na][1]));
                }
        }
        __syncthreads();
    }

    // epilogue
    #pragma unroll
    for (int ma = 0; ma < 4; ma++) {
        #pragma unroll
        for (int na = 0; na < 4; na++) {
            int col = n0 + wn * 32 + na * 8 + tig * 2;
            float b0 = bias[col], b1 = bias[col + 1];
            #pragma unroll
            for (int half = 0; half < 2; half++) {
                int row = m0 + wm * 64 + ma * 16 + gid + half * 8;
                float v0 = acc[ma][na][half * 2 + 0] + b0;
                float v1 = acc[ma][na][half * 2 + 1] + b1;
                if (EPI == 0) {
                    if (col < 2 * DI) {
                        v0 = v0 / (1.f + __expf(-v0));
                        v1 = v1 / (1.f + __expf(-v1));
                    }
                } else if (EPI == 1) {
                    v0 = fmaxf(v0, 0.f) + log1pf(__expf(-fabsf(v0)));
                    v1 = fmaxf(v1, 0.f) + log1pf(__expf(-fabsf(v1)));
                } else if (EPI == 2) {
                    v0 += resid[(long)row * DMD + col];
                    v1 += resid[(long)row * DMD + col + 1];
                }
                *(float2*)&C[(long)row * ldc + col] = make_float2(v0, v1);
            }
        }
    }
}

// ---------------- chunked selective scan + gating ----------------
__global__ void __launch_bounds__(384)
scan_kernel(const float* __restrict__ xz,
            const float* __restrict__ dt,
            const float* __restrict__ A_log,
            const float* __restrict__ D_vec,
            float* __restrict__ y)
{
    __shared__ float a2[DI * DS];
    int tid = threadIdx.x;
    for (int i = tid; i < DI * DS; i += DI)
        a2[i] = -expf(A_log[i]) * 1.4426950408889634f;
    __syncthreads();

    int di = tid;
    float av[DS];
    #pragma unroll
    for (int s = 0; s < DS; s++) av[s] = a2[di * DS + s];
    float dval = D_vec[di];

    long row0 = (long)blockIdx.x * CHUNK;
    float h[DS];
    #pragma unroll
    for (int s = 0; s < DS; s++) h[s] = 0.f;

    #pragma unroll 4
    for (int t = 0; t < CHUNK; t++) {
        long m  = row0 + t;
        float dtv = dt[m * DI + di];
        float xv  = xz[m * (3 * DI) + di];
        float zv  = xz[m * (3 * DI) + DI + di];
        float ys = 0.f;
        #pragma unroll
        for (int s = 0; s < DS; s++) {
            h[s] = fmaf(h[s], exp2f(dtv * av[s]), xv);
            ys += h[s];
        }
        y[m * DI + di] = fmaf(ys, zv, xv * dval);
    }
}

// ---------------- launch ----------------
#define SMEM_BYTES (4 * STAGE_SZ * 4)   // 73728 B

extern "C" void kernel_launch(void* const* d_in, const int* in_sizes, int n_in,
                              void* d_out, int out_size)
{
    const float* x     = (const float*)d_in[0];
    const float* gamma = (const float*)d_in[1];
    const float* beta  = (const float*)d_in[2];
    const float* W_in  = (const float*)d_in[3];
    const float* b_in  = (const float*)d_in[4];
    const float* W_dt  = (const float*)d_in[5];
    const float* b_dt  = (const float*)d_in[6];
    const float* A_log = (const float*)d_in[7];
    const float* D_vec = (const float*)d_in[8];
    const float* W_out = (const float*)d_in[9];
    const float* b_out = (const float*)d_in[10];
    float* out = (float*)d_out;

    float *xn, *xz, *dtb, *yb;
    cudaGetSymbolAddress((void**)&xn,  g_xn);
    cudaGetSymbolAddress((void**)&xz,  g_xz);
    cudaGetSymbolAddress((void**)&dtb, g_dt);
    cudaGetSymbolAddress((void**)&yb,  g_y);

    cudaFuncSetAttribute(mma_gemm<0>, cudaFuncAttributeMaxDynamicSharedMemorySize, SMEM_BYTES);
    cudaFuncSetAttribute(mma_gemm<1>, cudaFuncAttributeMaxDynamicSharedMemorySize, SMEM_BYTES);
    cudaFuncSetAttribute(mma_gemm<2>, cudaFuncAttributeMaxDynamicSharedMemorySize, SMEM_BYTES);

    // 1) LayerNorm
    ln_kernel<<<MTOK, DMD>>>(x, gamma, beta, xn);

    // 2) GEMM1: xz = xn @ W_in^T + b_in; silu on first 768 cols
    mma_gemm<0><<<dim3((3 * DI) / 128, MTOK / 128), 256, SMEM_BYTES>>>(
        xn, DMD, W_in, DMD, b_in, xz, 3 * DI, DMD, nullptr);

    // 3) GEMM2: dt = softplus(dt_in @ W_dt^T + b_dt)
    mma_gemm<1><<<dim3(DI / 128, MTOK / 128), 256, SMEM_BYTES>>>(
        xz + 2 * DI, 3 * DI, W_dt, DI, b_dt, dtb, DI, DI, nullptr);

    // 4) chunked scan + gating
    scan_kernel<<<NCHUNK, DI>>>(xz, dtb, A_log, D_vec, yb);

    // 5) GEMM3: out = y @ W_out^T + b_out + residual
    mma_gemm<2><<<dim3(DMD / 128, MTOK / 128), 256, SMEM_BYTES>>>(
        yb, DI, W_out, DI, b_out, out, DMD, DI, x);
}

// round 5
// speedup vs baseline: 2.8995x; 1.4508x over previous
#include <cuda_runtime.h>
#include <cuda_bf16.h>
#include <cstdint>
#include <math.h>

#define BB   8
#define LL   4096
#define DMD  256
#define DI   384
#define DS   8
#define CHUNK 32
#define MTOK (BB*LL)          // 32768
#define NCHUNK (MTOK/CHUNK)   // 1024

// ---------------- scratch (device globals; no allocation) ----------------
__device__ __nv_bfloat16 g_xn  [MTOK * DMD];      // LN out (bf16)        16 MB
__device__ float         g_xz  [MTOK * 2 * DI];   // silu(x_proj)|silu(z) 100 MB
__device__ __nv_bfloat16 g_dtin[MTOK * DI];       // raw dt_in (bf16)     25 MB
__device__ float         g_dt  [MTOK * DI];       // softplus out         50 MB
__device__ __nv_bfloat16 g_y   [MTOK * DI];       // scan out (bf16)      25 MB
__device__ __nv_bfloat16 g_Win [3 * DI * DMD];
__device__ __nv_bfloat16 g_Wdt [DI * DI];
__device__ __nv_bfloat16 g_Wout[DMD * DI];

// ---------------- helpers ----------------
__device__ __forceinline__ uint32_t smem_u32(const void* p) {
    uint32_t a;
    asm("{ .reg .u64 t; cvta.to.shared.u64 t, %1; cvt.u32.u64 %0, t; }" : "=r"(a) : "l"(p));
    return a;
}
__device__ __forceinline__ void cp16s(uint32_t s, const void* g) {
    asm volatile("cp.async.cg.shared.global [%0], [%1], 16;\n" :: "r"(s), "l"(g));
}
__device__ __forceinline__ void cp_commit() { asm volatile("cp.async.commit_group;\n"); }

// ---------------- weight fp32 -> bf16 prep ----------------
__global__ void cvt_w(const float* __restrict__ Win, const float* __restrict__ Wdt,
                      const float* __restrict__ Wout)
{
    int i = blockIdx.x * 256 + threadIdx.x;
    if (i < 3 * DI * DMD) g_Win[i]  = __float2bfloat16(Win[i]);
    if (i < DI * DI)      g_Wdt[i]  = __float2bfloat16(Wdt[i]);
    if (i < DMD * DI)     g_Wout[i] = __float2bfloat16(Wout[i]);
}

// ---------------- LayerNorm -> bf16 ----------------
__global__ void ln_kernel(const float* __restrict__ x,
                          const float* __restrict__ gamma,
                          const float* __restrict__ beta,
                          __nv_bfloat16* __restrict__ xn)
{
    int row = blockIdx.x;
    int t   = threadIdx.x;
    float v = x[(long)row * DMD + t];

    float s1 = v, s2 = v * v;
    #pragma unroll
    for (int o = 16; o; o >>= 1) {
        s1 += __shfl_xor_sync(0xffffffffu, s1, o);
        s2 += __shfl_xor_sync(0xffffffffu, s2, o);
    }
    __shared__ float red[16];
    int warp = t >> 5, lane = t & 31;
    if (lane == 0) { red[warp] = s1; red[8 + warp] = s2; }
    __syncthreads();
    if (t == 0) {
        float a = 0.f, b = 0.f;
        #pragma unroll
        for (int i = 0; i < 8; i++) { a += red[i]; b += red[8 + i]; }
        float mean = a * (1.0f / DMD);
        float var  = b * (1.0f / DMD) - mean * mean;
        red[0] = mean;
        red[8] = rsqrtf(var + 1e-5f);
    }
    __syncthreads();
    float mean = red[0], rstd = red[8];
    xn[(long)row * DMD + t] = __float2bfloat16((v - mean) * rstd * gamma[t] + beta[t]);
}

// ---------------- bf16 tensor-core GEMM ----------------
// C[M,N] = A[M,K] @ W[N,K]^T + bias (+epilogue). A,W bf16 row-major (K contig).
// Block 128x128, K-tile 32, 8 warps (2M x 4N), warp tile 64x32, 4-stage cp.async.
// smem rows padded to 40 bf16 (80 B) -> conflict-free ldmatrix.

#define NSTG 4
#define PADK 40
#define TILE_B (128 * PADK * 2)      // 10240 B per operand per stage
#define SMEM_G (2 * NSTG * TILE_B)   // 81920 B

__device__ __forceinline__ void ldsm4(uint32_t* r, uint32_t addr) {
    asm volatile("ldmatrix.sync.aligned.m8n8.x4.shared.b16 {%0,%1,%2,%3}, [%4];"
                 : "=r"(r[0]), "=r"(r[1]), "=r"(r[2]), "=r"(r[3]) : "r"(addr));
}
__device__ __forceinline__ void mma16816(float* d, const uint32_t* a, const uint32_t* b) {
    asm volatile(
        "mma.sync.aligned.m16n8k16.row.col.f32.bf16.bf16.f32 "
        "{%0,%1,%2,%3}, {%4,%5,%6,%7}, {%8,%9}, {%0,%1,%2,%3};\n"
        : "+f"(d[0]), "+f"(d[1]), "+f"(d[2]), "+f"(d[3])
        : "r"(a[0]), "r"(a[1]), "r"(a[2]), "r"(a[3]), "r"(b[0]), "r"(b[1]));
}

// EPI 0: GEMM1 -> n0<768: silu fp32 to Cf (ldcf=768); n0>=768: raw bf16 to Cb (col-768)
// EPI 1: softplus fp32 to Cf
// EPI 2: fp32 + resid to Cf
template <int EPI>
__global__ void __launch_bounds__(256, 1)
bf_gemm(const __nv_bfloat16* __restrict__ A, int lda,
        const __nv_bfloat16* __restrict__ W, int ldb,
        const float* __restrict__ bias,
        float* __restrict__ Cf, int ldcf,
        __nv_bfloat16* __restrict__ Cb,
        int K,
        const float* __restrict__ resid)
{
    extern __shared__ char smem[];
    uint32_t sbA = smem_u32(smem);
    uint32_t sbB = sbA + NSTG * TILE_B;

    int tid = threadIdx.x, wid = tid >> 5, lane = tid & 31;
    int wm = wid & 1, wn = wid >> 1;
    int gid = lane >> 2, tig = lane & 3;
    int m0 = blockIdx.y * 128, n0 = blockIdx.x * 128;
    int KT = K / 32;

    const __nv_bfloat16* Ag = A + (long)m0 * lda;
    const __nv_bfloat16* Wg = W + (long)n0 * ldb;

    // per-thread load coords: 2 chunks of 16B per operand per stage
    int c0 = tid;                 // chunk ids tid, tid+256 (512 chunks = 128 rows x 4)
    int r0l = c0 >> 2, k0l = (c0 & 3) * 8;
    int r1l = (c0 + 256) >> 2, k1l = ((c0 + 256) & 3) * 8;
    uint32_t so0 = (uint32_t)(r0l * (PADK * 2) + k0l * 2);
    uint32_t so1 = (uint32_t)(r1l * (PADK * 2) + k1l * 2);

    float acc[4][4][4];
    #pragma unroll
    for (int i = 0; i < 4; i++)
        #pragma unroll
        for (int j = 0; j < 4; j++)
            #pragma unroll
            for (int q = 0; q < 4; q++) acc[i][j][q] = 0.f;

    // prologue: stages 0..NSTG-2
    #pragma unroll
    for (int s = 0; s < NSTG - 1; s++) {
        uint32_t ab = sbA + s * TILE_B, bb = sbB + s * TILE_B;
        cp16s(ab + so0, Ag + (long)r0l * lda + s * 32 + k0l);
        cp16s(ab + so1, Ag + (long)r1l * lda + s * 32 + k1l);
        cp16s(bb + so0, Wg + (long)r0l * ldb + s * 32 + k0l);
        cp16s(bb + so1, Wg + (long)r1l * ldb + s * 32 + k1l);
        cp_commit();
    }

    for (int kt = 0; kt < KT; kt++) {
        asm volatile("cp.async.wait_group %0;" :: "n"(NSTG - 2));
        __syncthreads();

        int slot = kt & (NSTG - 1);
        uint32_t aS = sbA + slot * TILE_B;
        uint32_t bS = sbB + slot * TILE_B;

        #pragma unroll
        for (int kk = 0; kk < 2; kk++) {
            int kb = kk * 32;   // bytes: 16 bf16
            uint32_t af[4][4], bfr[4][2];
            #pragma unroll
            for (int ma = 0; ma < 4; ma++) {
                int r = wm * 64 + ma * 16 + (lane & 15);
                ldsm4(af[ma], aS + r * (PADK * 2) + kb + ((lane >> 4) & 1) * 16);
            }
            #pragma unroll
            for (int nb = 0; nb < 2; nb++) {
                int grp = lane >> 3;
                int nr = wn * 32 + (nb * 2 + (grp >> 1)) * 8 + (lane & 7);
                uint32_t t4[4];
                ldsm4(t4, bS + nr * (PADK * 2) + kb + (grp & 1) * 16);
                bfr[nb * 2][0] = t4[0]; bfr[nb * 2][1] = t4[1];
                bfr[nb * 2 + 1][0] = t4[2]; bfr[nb * 2 + 1][1] = t4[3];
            }
            #pragma unroll
            for (int ma = 0; ma < 4; ma++)
                #pragma unroll
                for (int na = 0; na < 4; na++)
                    mma16816(acc[ma][na], af[ma], bfr[na]);
        }
        __syncthreads();

        int nk = kt + NSTG - 1;
        if (nk < KT) {
            int s = nk & (NSTG - 1);
            uint32_t ab = sbA + s * TILE_B, bb = sbB + s * TILE_B;
            cp16s(ab + so0, Ag + (long)r0l * lda + nk * 32 + k0l);
            cp16s(ab + so1, Ag + (long)r1l * lda + nk * 32 + k1l);
            cp16s(bb + so0, Wg + (long)r0l * ldb + nk * 32 + k0l);
            cp16s(bb + so1, Wg + (long)r1l * ldb + nk * 32 + k1l);
        }
        cp_commit();
    }

    // epilogue
    bool bfreg = (EPI == 0) && (n0 >= 2 * DI);
    #pragma unroll
    for (int ma = 0; ma < 4; ma++) {
        #pragma unroll
        for (int na = 0; na < 4; na++) {
            int col = n0 + wn * 32 + na * 8 + tig * 2;
            float b0 = bias[col], b1 = bias[col + 1];
            #pragma unroll
            for (int half = 0; half < 2; half++) {
                int row = m0 + wm * 64 + ma * 16 + gid + half * 8;
                float v0 = acc[ma][na][half * 2 + 0] + b0;
                float v1 = acc[ma][na][half * 2 + 1] + b1;
                if (EPI == 0) {
                    if (!bfreg) {
                        v0 = v0 / (1.f + __expf(-v0));
                        v1 = v1 / (1.f + __expf(-v1));
                        *(float2*)&Cf[(long)row * ldcf + col] = make_float2(v0, v1);
                    } else {
                        __nv_bfloat162 o = __floats2bfloat162_rn(v0, v1);
                        *(__nv_bfloat162*)&Cb[(long)row * DI + (col - 2 * DI)] = o;
                    }
                } else if (EPI == 1) {
                    v0 = fmaxf(v0, 0.f) + log1pf(__expf(-fabsf(v0)));
                    v1 = fmaxf(v1, 0.f) + log1pf(__expf(-fabsf(v1)));
                    *(float2*)&Cf[(long)row * ldcf + col] = make_float2(v0, v1);
                } else {
                    v0 += resid[(long)row * DMD + col];
                    v1 += resid[(long)row * DMD + col + 1];
                    *(float2*)&Cf[(long)row * ldcf + col] = make_float2(v0, v1);
                }
            }
        }
    }
}

// ---------------- chunked selective scan + gating ----------------
__global__ void __launch_bounds__(384)
scan_kernel(const float* __restrict__ xz,
            const float* __restrict__ dt,
            const float* __restrict__ A_log,
            const float* __restrict__ D_vec,
            __nv_bfloat16* __restrict__ y)
{
    __shared__ float a2[DI * DS];
    int tid = threadIdx.x;
    for (int i = tid; i < DI * DS; i += DI)
        a2[i] = -expf(A_log[i]) * 1.4426950408889634f;
    __syncthreads();

    int di = tid;
    float av[DS];
    #pragma unroll
    for (int s = 0; s < DS; s++) av[s] = a2[di * DS + s];
    float dval = D_vec[di];

    long row0 = (long)blockIdx.x * CHUNK;
    float h[DS];
    #pragma unroll
    for (int s = 0; s < DS; s++) h[s] = 0.f;

    #pragma unroll 4
    for (int t = 0; t < CHUNK; t++) {
        long m  = row0 + t;
        float dtv = dt[m * DI + di];
        float xv  = xz[m * (2 * DI) + di];
        float zv  = xz[m * (2 * DI) + DI + di];
        float ys = 0.f;
        #pragma unroll
        for (int s = 0; s < DS; s++) {
            h[s] = fmaf(h[s], exp2f(dtv * av[s]), xv);
            ys += h[s];
        }
        y[m * DI + di] = __float2bfloat16(fmaf(ys, zv, xv * dval));
    }
}

// ---------------- launch ----------------
extern "C" void kernel_launch(void* const* d_in, const int* in_sizes, int n_in,
                              void* d_out, int out_size)
{
    const float* x     = (const float*)d_in[0];
    const float* gamma = (const float*)d_in[1];
    const float* beta  = (const float*)d_in[2];
    const float* W_in  = (const float*)d_in[3];
    const float* b_in  = (const float*)d_in[4];
    const float* W_dt  = (const float*)d_in[5];
    const float* b_dt  = (const float*)d_in[6];
    const float* A_log = (const float*)d_in[7];
    const float* D_vec = (const float*)d_in[8];
    const float* W_out = (const float*)d_in[9];
    const float* b_out = (const float*)d_in[10];
    float* out = (float*)d_out;

    __nv_bfloat16 *xn, *dtin, *yb, *win, *wdt, *wout;
    float *xz, *dtb;
    cudaGetSymbolAddress((void**)&xn,   g_xn);
    cudaGetSymbolAddress((void**)&xz,   g_xz);
    cudaGetSymbolAddress((void**)&dtin, g_dtin);
    cudaGetSymbolAddress((void**)&dtb,  g_dt);
    cudaGetSymbolAddress((void**)&yb,   g_y);
    cudaGetSymbolAddress((void**)&win,  g_Win);
    cudaGetSymbolAddress((void**)&wdt,  g_Wdt);
    cudaGetSymbolAddress((void**)&wout, g_Wout);

    cudaFuncSetAttribute(bf_gemm<0>, cudaFuncAttributeMaxDynamicSharedMemorySize, SMEM_G);
    cudaFuncSetAttribute(bf_gemm<1>, cudaFuncAttributeMaxDynamicSharedMemorySize, SMEM_G);
    cudaFuncSetAttribute(bf_gemm<2>, cudaFuncAttributeMaxDynamicSharedMemorySize, SMEM_G);

    // 0) weights -> bf16
    cvt_w<<<(3 * DI * DMD + 255) / 256, 256>>>(W_in, W_dt, W_out);

    // 1) LayerNorm -> bf16
    ln_kernel<<<MTOK, DMD>>>(x, gamma, beta, xn);

    // 2) GEMM1: [silu(x_proj)|silu(z)] fp32 -> g_xz ; raw dt_in bf16 -> g_dtin
    bf_gemm<0><<<dim3(9, MTOK / 128), 256, SMEM_G>>>(
        xn, DMD, win, DMD, b_in, xz, 2 * DI, dtin, DMD, nullptr);

    // 3) GEMM2: dt = softplus(dt_in @ W_dt^T + b_dt)
    bf_gemm<1><<<dim3(3, MTOK / 128), 256, SMEM_G>>>(
        dtin, DI, wdt, DI, b_dt, dtb, DI, nullptr, DI, nullptr);

    // 4) chunked scan + gating -> y (bf16)
    scan_kernel<<<NCHUNK, DI>>>(xz, dtb, A_log, D_vec, yb);

    // 5) GEMM3: out = y @ W_out^T + b_out + residual
    bf_gemm<2><<<dim3(2, MTOK / 128), 256, SMEM_G>>>(
        yb, DI, wout, DI, b_out, out, DMD, nullptr, DI, x);
}

// round 6
// speedup vs baseline: 3.1308x; 1.0798x over previous
#include <cuda_runtime.h>
#include <cuda_bf16.h>
#include <cstdint>
#include <math.h>

#define BB   8
#define LL   4096
#define DMD  256
#define DI   384
#define DS   8
#define CHUNK 32
#define MTOK (BB*LL)          // 32768
#define NCHUNK (MTOK/CHUNK)   // 1024

// ---------------- scratch (device globals; no allocation) ----------------
__device__ __nv_bfloat16 g_xn  [MTOK * DMD];
__device__ float         g_xz  [MTOK * 2 * DI];   // silu(x_proj)|silu(z)
__device__ __nv_bfloat16 g_dtin[MTOK * DI];
__device__ float         g_dt  [MTOK * DI];
__device__ __nv_bfloat16 g_y   [MTOK * DI];
__device__ __nv_bfloat16 g_Win [3 * DI * DMD];
__device__ __nv_bfloat16 g_Wdt [DI * DI];
__device__ __nv_bfloat16 g_Wout[DMD * DI];

// ---------------- helpers ----------------
__device__ __forceinline__ uint32_t smem_u32(const void* p) {
    uint32_t a;
    asm("{ .reg .u64 t; cvta.to.shared.u64 t, %1; cvt.u32.u64 %0, t; }" : "=r"(a) : "l"(p));
    return a;
}
__device__ __forceinline__ void cp16s(uint32_t s, const void* g) {
    asm volatile("cp.async.cg.shared.global [%0], [%1], 16;\n" :: "r"(s), "l"(g));
}
__device__ __forceinline__ void cp_commit() { asm volatile("cp.async.commit_group;\n"); }

// ---------------- weight fp32 -> bf16 prep ----------------
__global__ void cvt_w(const float* __restrict__ Win, const float* __restrict__ Wdt,
                      const float* __restrict__ Wout)
{
    int i = blockIdx.x * 256 + threadIdx.x;
    if (i < 3 * DI * DMD) g_Win[i]  = __float2bfloat16(Win[i]);
    if (i < DI * DI)      g_Wdt[i]  = __float2bfloat16(Wdt[i]);
    if (i < DMD * DI)     g_Wout[i] = __float2bfloat16(Wout[i]);
}

// ---------------- LayerNorm -> bf16 ----------------
__global__ void ln_kernel(const float* __restrict__ x,
                          const float* __restrict__ gamma,
                          const float* __restrict__ beta,
                          __nv_bfloat16* __restrict__ xn)
{
    int row = blockIdx.x;
    int t   = threadIdx.x;
    float v = x[(long)row * DMD + t];

    float s1 = v, s2 = v * v;
    #pragma unroll
    for (int o = 16; o; o >>= 1) {
        s1 += __shfl_xor_sync(0xffffffffu, s1, o);
        s2 += __shfl_xor_sync(0xffffffffu, s2, o);
    }
    __shared__ float red[16];
    int warp = t >> 5, lane = t & 31;
    if (lane == 0) { red[warp] = s1; red[8 + warp] = s2; }
    __syncthreads();
    if (t == 0) {
        float a = 0.f, b = 0.f;
        #pragma unroll
        for (int i = 0; i < 8; i++) { a += red[i]; b += red[8 + i]; }
        float mean = a * (1.0f / DMD);
        float var  = b * (1.0f / DMD) - mean * mean;
        red[0] = mean;
        red[8] = rsqrtf(var + 1e-5f);
    }
    __syncthreads();
    float mean = red[0], rstd = red[8];
    xn[(long)row * DMD + t] = __float2bfloat16((v - mean) * rstd * gamma[t] + beta[t]);
}

// ---------------- bf16 tensor-core GEMM ----------------
// C[M,N] = A[M,K] @ W[N,K]^T + bias (+epilogue). A,W bf16 row-major (K contig).
// Block tile 256x128, K-tile 32, 8 warps (2M x 4N), warp tile 128x32, 4-stage cp.async.
// smem rows padded to 40 bf16 (80 B).

#define NSTG 4
#define PADK 40
#define BM 256
#define ATILE_B (BM * PADK * 2)        // 20480 B / stage
#define BTILE_B (128 * PADK * 2)       // 10240 B / stage
#define SMEM_G (NSTG * (ATILE_B + BTILE_B))   // 122880 B

__device__ __forceinline__ void ldsm4(uint32_t* r, uint32_t addr) {
    asm volatile("ldmatrix.sync.aligned.m8n8.x4.shared.b16 {%0,%1,%2,%3}, [%4];"
                 : "=r"(r[0]), "=r"(r[1]), "=r"(r[2]), "=r"(r[3]) : "r"(addr));
}
__device__ __forceinline__ void mma16816(float* d, const uint32_t* a, const uint32_t* b) {
    asm volatile(
        "mma.sync.aligned.m16n8k16.row.col.f32.bf16.bf16.f32 "
        "{%0,%1,%2,%3}, {%4,%5,%6,%7}, {%8,%9}, {%0,%1,%2,%3};\n"
        : "+f"(d[0]), "+f"(d[1]), "+f"(d[2]), "+f"(d[3])
        : "r"(a[0]), "r"(a[1]), "r"(a[2]), "r"(a[3]), "r"(b[0]), "r"(b[1]));
}

// EPI 0: GEMM1 -> n0<768: silu fp32 to Cf; n0>=768: raw bf16 to Cb (col-768)
// EPI 1: softplus fp32 to Cf
// EPI 2: fp32 + resid to Cf
template <int EPI>
__global__ void __launch_bounds__(256, 1)
bf_gemm(const __nv_bfloat16* __restrict__ A, int lda,
        const __nv_bfloat16* __restrict__ W, int ldb,
        const float* __restrict__ bias,
        float* __restrict__ Cf, int ldcf,
        __nv_bfloat16* __restrict__ Cb,
        int K,
        const float* __restrict__ resid)
{
    extern __shared__ char smem[];
    uint32_t sbA = smem_u32(smem);
    uint32_t sbB = sbA + NSTG * ATILE_B;

    int tid = threadIdx.x, wid = tid >> 5, lane = tid & 31;
    int wm = wid & 1, wn = wid >> 1;
    int gid = lane >> 2, tig = lane & 3;
    int m0 = blockIdx.y * BM, n0 = blockIdx.x * 128;
    int KT = K / 32;

    const __nv_bfloat16* Ag = A + (long)m0 * lda;
    const __nv_bfloat16* Wg = W + (long)n0 * ldb;

    // load coords: A = 1024 chunks (4/thread), B = 512 chunks (2/thread)
    int ar[4], ak[4]; uint32_t aso[4];
    #pragma unroll
    for (int i = 0; i < 4; i++) {
        int c = tid + i * 256;
        ar[i] = c >> 2; ak[i] = (c & 3) * 8;
        aso[i] = (uint32_t)(ar[i] * (PADK * 2) + ak[i] * 2);
    }
    int br[2], bk[2]; uint32_t bso[2];
    #pragma unroll
    for (int i = 0; i < 2; i++) {
        int c = tid + i * 256;
        br[i] = c >> 2; bk[i] = (c & 3) * 8;
        bso[i] = (uint32_t)(br[i] * (PADK * 2) + bk[i] * 2);
    }

    float acc[8][4][4];
    #pragma unroll
    for (int i = 0; i < 8; i++)
        #pragma unroll
        for (int j = 0; j < 4; j++)
            #pragma unroll
            for (int q = 0; q < 4; q++) acc[i][j][q] = 0.f;

    // prologue: stages 0..NSTG-2
    #pragma unroll
    for (int s = 0; s < NSTG - 1; s++) {
        uint32_t ab = sbA + s * ATILE_B, bb = sbB + s * BTILE_B;
        #pragma unroll
        for (int i = 0; i < 4; i++)
            cp16s(ab + aso[i], Ag + (long)ar[i] * lda + s * 32 + ak[i]);
        #pragma unroll
        for (int i = 0; i < 2; i++)
            cp16s(bb + bso[i], Wg + (long)br[i] * ldb + s * 32 + bk[i]);
        cp_commit();
    }

    for (int kt = 0; kt < KT; kt++) {
        asm volatile("cp.async.wait_group %0;" :: "n"(NSTG - 2));
        __syncthreads();

        int slot = kt & (NSTG - 1);
        uint32_t aS = sbA + slot * ATILE_B;
        uint32_t bS = sbB + slot * BTILE_B;

        #pragma unroll
        for (int kk = 0; kk < 2; kk++) {
            int kb = kk * 32;   // byte offset of 16-k block
            uint32_t af[8][4], bfr[4][2];
            #pragma unroll
            for (int nb = 0; nb < 2; nb++) {
                int grp = lane >> 3;
                int nr = wn * 32 + (nb * 2 + (grp >> 1)) * 8 + (lane & 7);
                uint32_t t4[4];
                ldsm4(t4, bS + nr * (PADK * 2) + kb + (grp & 1) * 16);
                bfr[nb * 2][0] = t4[0]; bfr[nb * 2][1] = t4[1];
                bfr[nb * 2 + 1][0] = t4[2]; bfr[nb * 2 + 1][1] = t4[3];
            }
            #pragma unroll
            for (int ma = 0; ma < 8; ma++) {
                int r = wm * 128 + ma * 16 + (lane & 15);
                ldsm4(af[ma], aS + r * (PADK * 2) + kb + ((lane >> 4) & 1) * 16);
            }
            #pragma unroll
            for (int ma = 0; ma < 8; ma++)
                #pragma unroll
                for (int na = 0; na < 4; na++)
                    mma16816(acc[ma][na], af[ma], bfr[na]);
        }
        __syncthreads();

        int nk = kt + NSTG - 1;
        if (nk < KT) {
            int s = nk & (NSTG - 1);
            uint32_t ab = sbA + s * ATILE_B, bb = sbB + s * BTILE_B;
            #pragma unroll
            for (int i = 0; i < 4; i++)
                cp16s(ab + aso[i], Ag + (long)ar[i] * lda + nk * 32 + ak[i]);
            #pragma unroll
            for (int i = 0; i < 2; i++)
                cp16s(bb + bso[i], Wg + (long)br[i] * ldb + nk * 32 + bk[i]);
        }
        cp_commit();
    }

    // epilogue
    bool bfreg = (EPI == 0) && (n0 >= 2 * DI);
    #pragma unroll
    for (int ma = 0; ma < 8; ma++) {
        #pragma unroll
        for (int na = 0; na < 4; na++) {
            int col = n0 + wn * 32 + na * 8 + tig * 2;
            float b0 = bias[col], b1 = bias[col + 1];
            #pragma unroll
            for (int half = 0; half < 2; half++) {
                int row = m0 + wm * 128 + ma * 16 + gid + half * 8;
                float v0 = acc[ma][na][half * 2 + 0] + b0;
                float v1 = acc[ma][na][half * 2 + 1] + b1;
                if (EPI == 0) {
                    if (!bfreg) {
                        v0 = v0 / (1.f + __expf(-v0));
                        v1 = v1 / (1.f + __expf(-v1));
                        *(float2*)&Cf[(long)row * ldcf + col] = make_float2(v0, v1);
                    } else {
                        __nv_bfloat162 o = __floats2bfloat162_rn(v0, v1);
                        *(__nv_bfloat162*)&Cb[(long)row * DI + (col - 2 * DI)] = o;
                    }
                } else if (EPI == 1) {
                    v0 = fmaxf(v0, 0.f) + log1pf(__expf(-fabsf(v0)));
                    v1 = fmaxf(v1, 0.f) + log1pf(__expf(-fabsf(v1)));
                    *(float2*)&Cf[(long)row * ldcf + col] = make_float2(v0, v1);
                } else {
                    v0 += resid[(long)row * DMD + col];
                    v1 += resid[(long)row * DMD + col + 1];
                    *(float2*)&Cf[(long)row * ldcf + col] = make_float2(v0, v1);
                }
            }
        }
    }
}

// ---------------- chunked selective scan + gating ----------------
__global__ void __launch_bounds__(384)
scan_kernel(const float* __restrict__ xz,
            const float* __restrict__ dt,
            const float* __restrict__ A_log,
            const float* __restrict__ D_vec,
            __nv_bfloat16* __restrict__ y)
{
    __shared__ float a2[DI * DS];
    int tid = threadIdx.x;
    for (int i = tid; i < DI * DS; i += DI)
        a2[i] = -expf(A_log[i]) * 1.4426950408889634f;
    __syncthreads();

    int di = tid;
    float av[DS];
    #pragma unroll
    for (int s = 0; s < DS; s++) av[s] = a2[di * DS + s];
    float dval = D_vec[di];

    long row0 = (long)blockIdx.x * CHUNK;
    float h[DS];
    #pragma unroll
    for (int s = 0; s < DS; s++) h[s] = 0.f;

    #pragma unroll 4
    for (int t = 0; t < CHUNK; t++) {
        long m  = row0 + t;
        float dtv = dt[m * DI + di];
        float xv  = xz[m * (2 * DI) + di];
        float zv  = xz[m * (2 * DI) + DI + di];
        float ys = 0.f;
        #pragma unroll
        for (int s = 0; s < DS; s++) {
            h[s] = fmaf(h[s], exp2f(dtv * av[s]), xv);
            ys += h[s];
        }
        y[m * DI + di] = __float2bfloat16(fmaf(ys, zv, xv * dval));
    }
}

// ---------------- launch ----------------
extern "C" void kernel_launch(void* const* d_in, const int* in_sizes, int n_in,
                              void* d_out, int out_size)
{
    const float* x     = (const float*)d_in[0];
    const float* gamma = (const float*)d_in[1];
    const float* beta  = (const float*)d_in[2];
    const float* W_in  = (const float*)d_in[3];
    const float* b_in  = (const float*)d_in[4];
    const float* W_dt  = (const float*)d_in[5];
    const float* b_dt  = (const float*)d_in[6];
    const float* A_log = (const float*)d_in[7];
    const float* D_vec = (const float*)d_in[8];
    const float* W_out = (const float*)d_in[9];
    const float* b_out = (const float*)d_in[10];
    float* out = (float*)d_out;

    __nv_bfloat16 *xn, *dtin, *yb, *win, *wdt, *wout;
    float *xz, *dtb;
    cudaGetSymbolAddress((void**)&xn,   g_xn);
    cudaGetSymbolAddress((void**)&xz,   g_xz);
    cudaGetSymbolAddress((void**)&dtin, g_dtin);
    cudaGetSymbolAddress((void**)&dtb,  g_dt);
    cudaGetSymbolAddress((void**)&yb,   g_y);
    cudaGetSymbolAddress((void**)&win,  g_Win);
    cudaGetSymbolAddress((void**)&wdt,  g_Wdt);
    cudaGetSymbolAddress((void**)&wout, g_Wout);

    cudaFuncSetAttribute(bf_gemm<0>, cudaFuncAttributeMaxDynamicSharedMemorySize, SMEM_G);
    cudaFuncSetAttribute(bf_gemm<1>, cudaFuncAttributeMaxDynamicSharedMemorySize, SMEM_G);
    cudaFuncSetAttribute(bf_gemm<2>, cudaFuncAttributeMaxDynamicSharedMemorySize, SMEM_G);

    // 0) weights -> bf16
    cvt_w<<<(3 * DI * DMD + 255) / 256, 256>>>(W_in, W_dt, W_out);

    // 1) LayerNorm -> bf16
    ln_kernel<<<MTOK, DMD>>>(x, gamma, beta, xn);

    // 2) GEMM1: [silu(x_proj)|silu(z)] fp32 -> g_xz ; raw dt_in bf16 -> g_dtin
    bf_gemm<0><<<dim3(9, MTOK / BM), 256, SMEM_G>>>(
        xn, DMD, win, DMD, b_in, xz, 2 * DI, dtin, DMD, nullptr);

    // 3) GEMM2: dt = softplus(dt_in @ W_dt^T + b_dt)
    bf_gemm<1><<<dim3(3, MTOK / BM), 256, SMEM_G>>>(
        dtin, DI, wdt, DI, b_dt, dtb, DI, nullptr, DI, nullptr);

    // 4) chunked scan + gating -> y (bf16)
    scan_kernel<<<NCHUNK, DI>>>(xz, dtb, A_log, D_vec, yb);

    // 5) GEMM3: out = y @ W_out^T + b_out + residual
    bf_gemm<2><<<dim3(2, MTOK / BM), 256, SMEM_G>>>(
        yb, DI, wout, DI, b_out, out, DMD, nullptr, DI, x);
}

// round 7
// speedup vs baseline: 3.1744x; 1.0139x over previous
#include <cuda_runtime.h>
#include <cuda_bf16.h>
#include <cstdint>
#include <math.h>

#define BB   8
#define LL   4096
#define DMD  256
#define DI   384
#define DS   8
#define CHUNK 32
#define MTOK (BB*LL)          // 32768
#define NCHUNK (MTOK/CHUNK)   // 1024

// ---------------- scratch (device globals; no allocation) ----------------
__device__ __nv_bfloat16 g_xn  [MTOK * DMD];
__device__ float         g_xz  [MTOK * 2 * DI];   // silu(x_proj)|silu(z)
__device__ __nv_bfloat16 g_dtin[MTOK * DI];
__device__ float         g_dt  [MTOK * DI];
__device__ __nv_bfloat16 g_y   [MTOK * DI];
__device__ __nv_bfloat16 g_Win [3 * DI * DMD];
__device__ __nv_bfloat16 g_Wdt [DI * DI];
__device__ __nv_bfloat16 g_Wout[DMD * DI];

// ---------------- helpers ----------------
__device__ __forceinline__ uint32_t smem_u32(const void* p) {
    uint32_t a;
    asm("{ .reg .u64 t; cvta.to.shared.u64 t, %1; cvt.u32.u64 %0, t; }" : "=r"(a) : "l"(p));
    return a;
}
__device__ __forceinline__ void cp16s(uint32_t s, const void* g) {
    asm volatile("cp.async.cg.shared.global [%0], [%1], 16;\n" :: "r"(s), "l"(g));
}
__device__ __forceinline__ void cp_commit() { asm volatile("cp.async.commit_group;\n"); }

// ---------------- weight fp32 -> bf16 prep ----------------
__global__ void cvt_w(const float* __restrict__ Win, const float* __restrict__ Wdt,
                      const float* __restrict__ Wout)
{
    int i = blockIdx.x * 256 + threadIdx.x;
    if (i < 3 * DI * DMD) g_Win[i]  = __float2bfloat16(Win[i]);
    if (i < DI * DI)      g_Wdt[i]  = __float2bfloat16(Wdt[i]);
    if (i < DMD * DI)     g_Wout[i] = __float2bfloat16(Wout[i]);
}

// ---------------- LayerNorm -> bf16 ----------------
__global__ void ln_kernel(const float* __restrict__ x,
                          const float* __restrict__ gamma,
                          const float* __restrict__ beta,
                          __nv_bfloat16* __restrict__ xn)
{
    int row = blockIdx.x;
    int t   = threadIdx.x;
    float v = x[(long)row * DMD + t];

    float s1 = v, s2 = v * v;
    #pragma unroll
    for (int o = 16; o; o >>= 1) {
        s1 += __shfl_xor_sync(0xffffffffu, s1, o);
        s2 += __shfl_xor_sync(0xffffffffu, s2, o);
    }
    __shared__ float red[16];
    int warp = t >> 5, lane = t & 31;
    if (lane == 0) { red[warp] = s1; red[8 + warp] = s2; }
    __syncthreads();
    if (t == 0) {
        float a = 0.f, b = 0.f;
        #pragma unroll
        for (int i = 0; i < 8; i++) { a += red[i]; b += red[8 + i]; }
        float mean = a * (1.0f / DMD);
        float var  = b * (1.0f / DMD) - mean * mean;
        red[0] = mean;
        red[8] = rsqrtf(var + 1e-5f);
    }
    __syncthreads();
    float mean = red[0], rstd = red[8];
    xn[(long)row * DMD + t] = __float2bfloat16((v - mean) * rstd * gamma[t] + beta[t]);
}

// ---------------- bf16 tensor-core GEMM ----------------
// C[M,N] = A[M,K] @ W[N,K]^T + bias (+epilogue). A,W bf16 row-major (K contig).
// Block tile 128x128, K-tile 32, 512 threads = 16 warps (4M x 4N), warp tile 32x32.
// 4-stage cp.async pipeline; rows padded to 40 bf16 (80 B).

#define NSTG 4
#define PADK 40
#define TILE_B (128 * PADK * 2)        // 10240 B per operand per stage
#define SMEM_G (2 * NSTG * TILE_B)     // 81920 B

__device__ __forceinline__ void ldsm4(uint32_t* r, uint32_t addr) {
    asm volatile("ldmatrix.sync.aligned.m8n8.x4.shared.b16 {%0,%1,%2,%3}, [%4];"
                 : "=r"(r[0]), "=r"(r[1]), "=r"(r[2]), "=r"(r[3]) : "r"(addr));
}
__device__ __forceinline__ void mma16816(float* d, const uint32_t* a, const uint32_t* b) {
    asm volatile(
        "mma.sync.aligned.m16n8k16.row.col.f32.bf16.bf16.f32 "
        "{%0,%1,%2,%3}, {%4,%5,%6,%7}, {%8,%9}, {%0,%1,%2,%3};\n"
        : "+f"(d[0]), "+f"(d[1]), "+f"(d[2]), "+f"(d[3])
        : "r"(a[0]), "r"(a[1]), "r"(a[2]), "r"(a[3]), "r"(b[0]), "r"(b[1]));
}

// EPI 0: GEMM1 -> n0<768: silu fp32 to Cf; n0>=768: raw bf16 to Cb (col-768)
// EPI 1: softplus fp32 to Cf
// EPI 2: fp32 + resid to Cf
template <int EPI>
__global__ void __launch_bounds__(512, 1)
bf_gemm(const __nv_bfloat16* __restrict__ A, int lda,
        const __nv_bfloat16* __restrict__ W, int ldb,
        const float* __restrict__ bias,
        float* __restrict__ Cf, int ldcf,
        __nv_bfloat16* __restrict__ Cb,
        int K,
        const float* __restrict__ resid)
{
    extern __shared__ char smem[];
    uint32_t sbA = smem_u32(smem);
    uint32_t sbB = sbA + NSTG * TILE_B;

    int tid = threadIdx.x, wid = tid >> 5, lane = tid & 31;
    int wm = wid & 3, wn = wid >> 2;           // 4x4 warp grid
    int gid = lane >> 2, tig = lane & 3;
    int m0 = blockIdx.y * 128, n0 = blockIdx.x * 128;
    int KT = K / 32;

    const __nv_bfloat16* Ag = A + (long)m0 * lda;
    const __nv_bfloat16* Wg = W + (long)n0 * ldb;

    // load coords: 512 chunks of 16B per operand per stage, one per thread
    int lr = tid >> 2, lk = (tid & 3) * 8;
    uint32_t so = (uint32_t)(lr * (PADK * 2) + lk * 2);

    float acc[2][4][4];
    #pragma unroll
    for (int i = 0; i < 2; i++)
        #pragma unroll
        for (int j = 0; j < 4; j++)
            #pragma unroll
            for (int q = 0; q < 4; q++) acc[i][j][q] = 0.f;

    // prologue: stages 0..NSTG-2
    #pragma unroll
    for (int s = 0; s < NSTG - 1; s++) {
        cp16s(sbA + s * TILE_B + so, Ag + (long)lr * lda + s * 32 + lk);
        cp16s(sbB + s * TILE_B + so, Wg + (long)lr * ldb + s * 32 + lk);
        cp_commit();
    }

    for (int kt = 0; kt < KT; kt++) {
        asm volatile("cp.async.wait_group %0;" :: "n"(NSTG - 2));
        __syncthreads();

        // issue next-stage loads first so they overlap the MMA burst
        int nk = kt + NSTG - 1;
        if (nk < KT) {
            int s = nk & (NSTG - 1);
            cp16s(sbA + s * TILE_B + so, Ag + (long)lr * lda + nk * 32 + lk);
            cp16s(sbB + s * TILE_B + so, Wg + (long)lr * ldb + nk * 32 + lk);
        }
        cp_commit();

        int slot = kt & (NSTG - 1);
        uint32_t aS = sbA + slot * TILE_B;
        uint32_t bS = sbB + slot * TILE_B;

        #pragma unroll
        for (int kk = 0; kk < 2; kk++) {
            int kb = kk * 32;
            uint32_t af[2][4], bfr[4][2];
            #pragma unroll
            for (int nb = 0; nb < 2; nb++) {
                int grp = lane >> 3;
                int nr = wn * 32 + (nb * 2 + (grp >> 1)) * 8 + (lane & 7);
                uint32_t t4[4];
                ldsm4(t4, bS + nr * (PADK * 2) + kb + (grp & 1) * 16);
                bfr[nb * 2][0] = t4[0]; bfr[nb * 2][1] = t4[1];
                bfr[nb * 2 + 1][0] = t4[2]; bfr[nb * 2 + 1][1] = t4[3];
            }
            #pragma unroll
            for (int ma = 0; ma < 2; ma++) {
                int r = wm * 32 + ma * 16 + (lane & 15);
                ldsm4(af[ma], aS + r * (PADK * 2) + kb + ((lane >> 4) & 1) * 16);
            }
            #pragma unroll
            for (int ma = 0; ma < 2; ma++)
                #pragma unroll
                for (int na = 0; na < 4; na++)
                    mma16816(acc[ma][na], af[ma], bfr[na]);
        }
        // no second barrier needed: the top-of-iteration barrier at kt+1 already
        // orders compute(kt) before the slot-(kt) overwrite at iteration kt+1.
    }

    // epilogue
    bool bfreg = (EPI == 0) && (n0 >= 2 * DI);
    #pragma unroll
    for (int ma = 0; ma < 2; ma++) {
        #pragma unroll
        for (int na = 0; na < 4; na++) {
            int col = n0 + wn * 32 + na * 8 + tig * 2;
            float b0 = bias[col], b1 = bias[col + 1];
            #pragma unroll
            for (int half = 0; half < 2; half++) {
                int row = m0 + wm * 32 + ma * 16 + gid + half * 8;
                float v0 = acc[ma][na][half * 2 + 0] + b0;
                float v1 = acc[ma][na][half * 2 + 1] + b1;
                if (EPI == 0) {
                    if (!bfreg) {
                        v0 = v0 / (1.f + __expf(-v0));
                        v1 = v1 / (1.f + __expf(-v1));
                        *(float2*)&Cf[(long)row * ldcf + col] = make_float2(v0, v1);
                    } else {
                        __nv_bfloat162 o = __floats2bfloat162_rn(v0, v1);
                        *(__nv_bfloat162*)&Cb[(long)row * DI + (col - 2 * DI)] = o;
                    }
                } else if (EPI == 1) {
                    v0 = fmaxf(v0, 0.f) + log1pf(__expf(-fabsf(v0)));
                    v1 = fmaxf(v1, 0.f) + log1pf(__expf(-fabsf(v1)));
                    *(float2*)&Cf[(long)row * ldcf + col] = make_float2(v0, v1);
                } else {
                    v0 += resid[(long)row * DMD + col];
                    v1 += resid[(long)row * DMD + col + 1];
                    *(float2*)&Cf[(long)row * ldcf + col] = make_float2(v0, v1);
                }
            }
        }
    }
}

// ---------------- chunked selective scan + gating ----------------
__global__ void __launch_bounds__(384)
scan_kernel(const float* __restrict__ xz,
            const float* __restrict__ dt,
            const float* __restrict__ A_log,
            const float* __restrict__ D_vec,
            __nv_bfloat16* __restrict__ y)
{
    __shared__ float a2[DI * DS];
    int tid = threadIdx.x;
    for (int i = tid; i < DI * DS; i += DI)
        a2[i] = -expf(A_log[i]) * 1.4426950408889634f;
    __syncthreads();

    int di = tid;
    float av[DS];
    #pragma unroll
    for (int s = 0; s < DS; s++) av[s] = a2[di * DS + s];
    float dval = D_vec[di];

    long row0 = (long)blockIdx.x * CHUNK;
    float h[DS];
    #pragma unroll
    for (int s = 0; s < DS; s++) h[s] = 0.f;

    #pragma unroll 4
    for (int t = 0; t < CHUNK; t++) {
        long m  = row0 + t;
        float dtv = dt[m * DI + di];
        float xv  = xz[m * (2 * DI) + di];
        float zv  = xz[m * (2 * DI) + DI + di];
        float ys = 0.f;
        #pragma unroll
        for (int s = 0; s < DS; s++) {
            h[s] = fmaf(h[s], exp2f(dtv * av[s]), xv);
            ys += h[s];
        }
        y[m * DI + di] = __float2bfloat16(fmaf(ys, zv, xv * dval));
    }
}

// ---------------- launch ----------------
extern "C" void kernel_launch(void* const* d_in, const int* in_sizes, int n_in,
                              void* d_out, int out_size)
{
    const float* x     = (const float*)d_in[0];
    const float* gamma = (const float*)d_in[1];
    const float* beta  = (const float*)d_in[2];
    const float* W_in  = (const float*)d_in[3];
    const float* b_in  = (const float*)d_in[4];
    const float* W_dt  = (const float*)d_in[5];
    const float* b_dt  = (const float*)d_in[6];
    const float* A_log = (const float*)d_in[7];
    const float* D_vec = (const float*)d_in[8];
    const float* W_out = (const float*)d_in[9];
    const float* b_out = (const float*)d_in[10];
    float* out = (float*)d_out;

    __nv_bfloat16 *xn, *dtin, *yb, *win, *wdt, *wout;
    float *xz, *dtb;
    cudaGetSymbolAddress((void**)&xn,   g_xn);
    cudaGetSymbolAddress((void**)&xz,   g_xz);
    cudaGetSymbolAddress((void**)&dtin, g_dtin);
    cudaGetSymbolAddress((void**)&dtb,  g_dt);
    cudaGetSymbolAddress((void**)&yb,   g_y);
    cudaGetSymbolAddress((void**)&win,  g_Win);
    cudaGetSymbolAddress((void**)&wdt,  g_Wdt);
    cudaGetSymbolAddress((void**)&wout, g_Wout);

    cudaFuncSetAttribute(bf_gemm<0>, cudaFuncAttributeMaxDynamicSharedMemorySize, SMEM_G);
    cudaFuncSetAttribute(bf_gemm<1>, cudaFuncAttributeMaxDynamicSharedMemorySize, SMEM_G);
    cudaFuncSetAttribute(bf_gemm<2>, cudaFuncAttributeMaxDynamicSharedMemorySize, SMEM_G);

    // 0) weights -> bf16
    cvt_w<<<(3 * DI * DMD + 255) / 256, 256>>>(W_in, W_dt, W_out);

    // 1) LayerNorm -> bf16
    ln_kernel<<<MTOK, DMD>>>(x, gamma, beta, xn);

    // 2) GEMM1: [silu(x_proj)|silu(z)] fp32 -> g_xz ; raw dt_in bf16 -> g_dtin
    bf_gemm<0><<<dim3(9, MTOK / 128), 512, SMEM_G>>>(
        xn, DMD, win, DMD, b_in, xz, 2 * DI, dtin, DMD, nullptr);

    // 3) GEMM2: dt = softplus(dt_in @ W_dt^T + b_dt)
    bf_gemm<1><<<dim3(3, MTOK / 128), 512, SMEM_G>>>(
        dtin, DI, wdt, DI, b_dt, dtb, DI, nullptr, DI, nullptr);

    // 4) chunked scan + gating -> y (bf16)
    scan_kernel<<<NCHUNK, DI>>>(xz, dtb, A_log, D_vec, yb);

    // 5) GEMM3: out = y @ W_out^T + b_out + residual
    bf_gemm<2><<<dim3(2, MTOK / 128), 512, SMEM_G>>>(
        yb, DI, wout, DI, b_out, out, DMD, nullptr, DI, x);
}

// round 8
// speedup vs baseline: 3.2548x; 1.0253x over previous
#include <cuda_runtime.h>
#include <cuda_bf16.h>
#include <cstdint>
#include <math.h>

#define BB   8
#define LL   4096
#define DMD  256
#define DI   384
#define DS   8
#define CHUNK 32
#define MTOK (BB*LL)          // 32768
#define NCHUNK (MTOK/CHUNK)   // 1024

// ---------------- scratch (device globals; no allocation) ----------------
__device__ __nv_bfloat16 g_xn  [MTOK * DMD];
__device__ float         g_xz  [MTOK * 2 * DI];   // silu(x_proj)|silu(z)
__device__ __nv_bfloat16 g_dtin[MTOK * DI];
__device__ float         g_dt  [MTOK * DI];
__device__ __nv_bfloat16 g_y   [MTOK * DI];
__device__ __nv_bfloat16 g_Win [3 * DI * DMD];
__device__ __nv_bfloat16 g_Wdt [DI * DI];
__device__ __nv_bfloat16 g_Wout[DMD * DI];

// ---------------- helpers ----------------
__device__ __forceinline__ uint32_t smem_u32(const void* p) {
    uint32_t a;
    asm("{ .reg .u64 t; cvta.to.shared.u64 t, %1; cvt.u32.u64 %0, t; }" : "=r"(a) : "l"(p));
    return a;
}
__device__ __forceinline__ void cp16s(uint32_t s, const void* g) {
    asm volatile("cp.async.cg.shared.global [%0], [%1], 16;\n" :: "r"(s), "l"(g));
}
__device__ __forceinline__ void cp_commit() { asm volatile("cp.async.commit_group;\n"); }

// ---------------- weight fp32 -> bf16 prep ----------------
__global__ void cvt_w(const float* __restrict__ Win, const float* __restrict__ Wdt,
                      const float* __restrict__ Wout)
{
    int i = blockIdx.x * 256 + threadIdx.x;
    if (i < 3 * DI * DMD) g_Win[i]  = __float2bfloat16(Win[i]);
    if (i < DI * DI)      g_Wdt[i]  = __float2bfloat16(Wdt[i]);
    if (i < DMD * DI)     g_Wout[i] = __float2bfloat16(Wout[i]);
}

// ---------------- LayerNorm -> bf16 ----------------
__global__ void ln_kernel(const float* __restrict__ x,
                          const float* __restrict__ gamma,
                          const float* __restrict__ beta,
                          __nv_bfloat16* __restrict__ xn)
{
    int row = blockIdx.x;
    int t   = threadIdx.x;
    float v = x[(long)row * DMD + t];

    float s1 = v, s2 = v * v;
    #pragma unroll
    for (int o = 16; o; o >>= 1) {
        s1 += __shfl_xor_sync(0xffffffffu, s1, o);
        s2 += __shfl_xor_sync(0xffffffffu, s2, o);
    }
    __shared__ float red[16];
    int warp = t >> 5, lane = t & 31;
    if (lane == 0) { red[warp] = s1; red[8 + warp] = s2; }
    __syncthreads();
    if (t == 0) {
        float a = 0.f, b = 0.f;
        #pragma unroll
        for (int i = 0; i < 8; i++) { a += red[i]; b += red[8 + i]; }
        float mean = a * (1.0f / DMD);
        float var  = b * (1.0f / DMD) - mean * mean;
        red[0] = mean;
        red[8] = rsqrtf(var + 1e-5f);
    }
    __syncthreads();
    float mean = red[0], rstd = red[8];
    xn[(long)row * DMD + t] = __float2bfloat16((v - mean) * rstd * gamma[t] + beta[t]);
}

// ---------------- bf16 tensor-core GEMM ----------------
// C[M,N] = A[M,K] @ W[N,K]^T + bias (+epilogue). A,W bf16 row-major (K contig).
// Block tile 128x128, K-tile 64 (4 kk-steps), 512 thr = 16 warps (4Mx4N),
// warp tile 32x32, NSTG=3 cp.async pipeline, fragment double-buffering.
// smem rows padded to 72 bf16 (144 B -> 4-bank row rotation, ldsm conflict-free).

#define NSTG 3
#define PADK 72
#define TILE_B (128 * PADK * 2)        // 18432 B per operand per stage
#define SMEM_G (2 * NSTG * TILE_B)     // 110592 B

__device__ __forceinline__ void ldsm4(uint32_t* r, uint32_t addr) {
    asm volatile("ldmatrix.sync.aligned.m8n8.x4.shared.b16 {%0,%1,%2,%3}, [%4];"
                 : "=r"(r[0]), "=r"(r[1]), "=r"(r[2]), "=r"(r[3]) : "r"(addr));
}
__device__ __forceinline__ void mma16816(float* d, const uint32_t* a, const uint32_t* b) {
    asm volatile(
        "mma.sync.aligned.m16n8k16.row.col.f32.bf16.bf16.f32 "
        "{%0,%1,%2,%3}, {%4,%5,%6,%7}, {%8,%9}, {%0,%1,%2,%3};\n"
        : "+f"(d[0]), "+f"(d[1]), "+f"(d[2]), "+f"(d[3])
        : "r"(a[0]), "r"(a[1]), "r"(a[2]), "r"(a[3]), "r"(b[0]), "r"(b[1]));
}

// EPI 0: GEMM1 -> n0<768: silu fp32 to Cf; n0>=768: raw bf16 to Cb (col-768)
// EPI 1: softplus fp32 to Cf
// EPI 2: fp32 + resid to Cf
template <int EPI>
__global__ void __launch_bounds__(512, 1)
bf_gemm(const __nv_bfloat16* __restrict__ A, int lda,
        const __nv_bfloat16* __restrict__ W, int ldb,
        const float* __restrict__ bias,
        float* __restrict__ Cf, int ldcf,
        __nv_bfloat16* __restrict__ Cb,
        int K,
        const float* __restrict__ resid)
{
    extern __shared__ char smem[];
    uint32_t sbA = smem_u32(smem);
    uint32_t sbB = sbA + NSTG * TILE_B;

    int tid = threadIdx.x, wid = tid >> 5, lane = tid & 31;
    int wm = wid & 3, wn = wid >> 2;           // 4x4 warp grid
    int gid = lane >> 2, tig = lane & 3;
    int m0 = blockIdx.y * 128, n0 = blockIdx.x * 128;
    int KT = K / 64;

    const __nv_bfloat16* Ag = A + (long)m0 * lda;
    const __nv_bfloat16* Wg = W + (long)n0 * ldb;

    // loads: per stage per operand = 128 rows x 128B = 1024 chunks of 16B; 2/thread
    int lr0 = tid >> 3,          lk0 = (tid & 7) * 8;
    int lr1 = (tid + 512) >> 3,  lk1 = ((tid + 512) & 7) * 8;
    uint32_t so0 = (uint32_t)(lr0 * (PADK * 2) + lk0 * 2);
    uint32_t so1 = (uint32_t)(lr1 * (PADK * 2) + lk1 * 2);

    // ldsm base addresses (within a stage)
    int arow = wm * 32 + (lane & 15);
    uint32_t aoff = (uint32_t)(arow * (PADK * 2) + ((lane >> 4) & 1) * 16);
    int grp = lane >> 3;
    int brow = wn * 32 + ((grp >> 1) * 8) + (lane & 7);
    uint32_t boff = (uint32_t)(brow * (PADK * 2) + (grp & 1) * 16);

    float acc[2][4][4];
    #pragma unroll
    for (int i = 0; i < 2; i++)
        #pragma unroll
        for (int j = 0; j < 4; j++)
            #pragma unroll
            for (int q = 0; q < 4; q++) acc[i][j][q] = 0.f;

    // prologue: stages 0..NSTG-2
    #pragma unroll
    for (int s = 0; s < NSTG - 1; s++) {
        cp16s(sbA + s * TILE_B + so0, Ag + (long)lr0 * lda + s * 64 + lk0);
        cp16s(sbA + s * TILE_B + so1, Ag + (long)lr1 * lda + s * 64 + lk1);
        cp16s(sbB + s * TILE_B + so0, Wg + (long)lr0 * ldb + s * 64 + lk0);
        cp16s(sbB + s * TILE_B + so1, Wg + (long)lr1 * ldb + s * 64 + lk1);
        cp_commit();
    }

    uint32_t af[2][2][4], bfr[2][4][2];   // [buf][frag...]

    for (int kt = 0; kt < KT; kt++) {
        asm volatile("cp.async.wait_group %0;" :: "n"(NSTG - 2));
        __syncthreads();

        int slot = kt % NSTG;
        uint32_t aS = sbA + slot * TILE_B;
        uint32_t bS = sbB + slot * TILE_B;

        // prefetch fragments for kk=0 into buf 0
        {
            uint32_t t4[4];
            ldsm4(t4, bS + boff);
            bfr[0][grp >> 1 ? 2 : 0][0] = 0; // (placeholder removed below)
            bfr[0][0][0] = t4[0]; bfr[0][0][1] = t4[1];
            bfr[0][1][0] = t4[2]; bfr[0][1][1] = t4[3];
            ldsm4(t4, bS + boff + 16 * (PADK * 2));
            bfr[0][2][0] = t4[0]; bfr[0][2][1] = t4[1];
            bfr[0][3][0] = t4[2]; bfr[0][3][1] = t4[3];
            ldsm4(af[0][0], aS + aoff);
            ldsm4(af[0][1], aS + aoff + 16 * (PADK * 2));
        }

        // issue next-stage gmem loads inside the ldsm shadow
        int nk = kt + NSTG - 1;
        if (nk < KT) {
            int s = nk % NSTG;
            cp16s(sbA + s * TILE_B + so0, Ag + (long)lr0 * lda + nk * 64 + lk0);
            cp16s(sbA + s * TILE_B + so1, Ag + (long)lr1 * lda + nk * 64 + lk1);
            cp16s(sbB + s * TILE_B + so0, Wg + (long)lr0 * ldb + nk * 64 + lk0);
            cp16s(sbB + s * TILE_B + so1, Wg + (long)lr1 * ldb + nk * 64 + lk1);
        }
        cp_commit();

        #pragma unroll
        for (int kk = 0; kk < 4; kk++) {
            int cur = kk & 1, nxt = cur ^ 1;
            if (kk < 3) {
                int kb = (kk + 1) * 32;
                uint32_t t4[4];
                ldsm4(t4, bS + boff + kb);
                bfr[nxt][0][0] = t4[0]; bfr[nxt][0][1] = t4[1];
                bfr[nxt][1][0] = t4[2]; bfr[nxt][1][1] = t4[3];
                ldsm4(t4, bS + boff + 16 * (PADK * 2) + kb);
                bfr[nxt][2][0] = t4[0]; bfr[nxt][2][1] = t4[1];
                bfr[nxt][3][0] = t4[2]; bfr[nxt][3][1] = t4[3];
                ldsm4(af[nxt][0], aS + aoff + kb);
                ldsm4(af[nxt][1], aS + aoff + 16 * (PADK * 2) + kb);
            }
            #pragma unroll
            for (int ma = 0; ma < 2; ma++)
                #pragma unroll
                for (int na = 0; na < 4; na++)
                    mma16816(acc[ma][na], af[cur][ma], bfr[cur][na]);
        }
    }

    // epilogue
    bool bfreg = (EPI == 0) && (n0 >= 2 * DI);
    #pragma unroll
    for (int ma = 0; ma < 2; ma++) {
        #pragma unroll
        for (int na = 0; na < 4; na++) {
            int col = n0 + wn * 32 + na * 8 + tig * 2;
            float b0 = bias[col], b1 = bias[col + 1];
            #pragma unroll
            for (int half = 0; half < 2; half++) {
                int row = m0 + wm * 32 + ma * 16 + gid + half * 8;
                float v0 = acc[ma][na][half * 2 + 0] + b0;
                float v1 = acc[ma][na][half * 2 + 1] + b1;
                if (EPI == 0) {
                    if (!bfreg) {
                        v0 = v0 / (1.f + __expf(-v0));
                        v1 = v1 / (1.f + __expf(-v1));
                        *(float2*)&Cf[(long)row * ldcf + col] = make_float2(v0, v1);
                    } else {
                        __nv_bfloat162 o = __floats2bfloat162_rn(v0, v1);
                        *(__nv_bfloat162*)&Cb[(long)row * DI + (col - 2 * DI)] = o;
                    }
                } else if (EPI == 1) {
                    v0 = fmaxf(v0, 0.f) + log1pf(__expf(-fabsf(v0)));
                    v1 = fmaxf(v1, 0.f) + log1pf(__expf(-fabsf(v1)));
                    *(float2*)&Cf[(long)row * ldcf + col] = make_float2(v0, v1);
                } else {
                    v0 += resid[(long)row * DMD + col];
                    v1 += resid[(long)row * DMD + col + 1];
                    *(float2*)&Cf[(long)row * ldcf + col] = make_float2(v0, v1);
                }
            }
        }
    }
}

// ---------------- chunked selective scan + gating ----------------
__global__ void __launch_bounds__(384)
scan_kernel(const float* __restrict__ xz,
            const float* __restrict__ dt,
            const float* __restrict__ A_log,
            const float* __restrict__ D_vec,
            __nv_bfloat16* __restrict__ y)
{
    __shared__ float a2[DI * DS];
    int tid = threadIdx.x;
    for (int i = tid; i < DI * DS; i += DI)
        a2[i] = -expf(A_log[i]) * 1.4426950408889634f;
    __syncthreads();

    int di = tid;
    float av[DS];
    #pragma unroll
    for (int s = 0; s < DS; s++) av[s] = a2[di * DS + s];
    float dval = D_vec[di];

    long row0 = (long)blockIdx.x * CHUNK;
    float h[DS];
    #pragma unroll
    for (int s = 0; s < DS; s++) h[s] = 0.f;

    #pragma unroll 4
    for (int t = 0; t < CHUNK; t++) {
        long m  = row0 + t;
        float dtv = dt[m * DI + di];
        float xv  = xz[m * (2 * DI) + di];
        float zv  = xz[m * (2 * DI) + DI + di];
        float ys = 0.f;
        #pragma unroll
        for (int s = 0; s < DS; s++) {
            h[s] = fmaf(h[s], exp2f(dtv * av[s]), xv);
            ys += h[s];
        }
        y[m * DI + di] = __float2bfloat16(fmaf(ys, zv, xv * dval));
    }
}

// ---------------- launch ----------------
extern "C" void kernel_launch(void* const* d_in, const int* in_sizes, int n_in,
                              void* d_out, int out_size)
{
    const float* x     = (const float*)d_in[0];
    const float* gamma = (const float*)d_in[1];
    const float* beta  = (const float*)d_in[2];
    const float* W_in  = (const float*)d_in[3];
    const float* b_in  = (const float*)d_in[4];
    const float* W_dt  = (const float*)d_in[5];
    const float* b_dt  = (const float*)d_in[6];
    const float* A_log = (const float*)d_in[7];
    const float* D_vec = (const float*)d_in[8];
    const float* W_out = (const float*)d_in[9];
    const float* b_out = (const float*)d_in[10];
    float* out = (float*)d_out;

    __nv_bfloat16 *xn, *dtin, *yb, *win, *wdt, *wout;
    float *xz, *dtb;
    cudaGetSymbolAddress((void**)&xn,   g_xn);
    cudaGetSymbolAddress((void**)&xz,   g_xz);
    cudaGetSymbolAddress((void**)&dtin, g_dtin);
    cudaGetSymbolAddress((void**)&dtb,  g_dt);
    cudaGetSymbolAddress((void**)&yb,   g_y);
    cudaGetSymbolAddress((void**)&win,  g_Win);
    cudaGetSymbolAddress((void**)&wdt,  g_Wdt);
    cudaGetSymbolAddress((void**)&wout, g_Wout);

    cudaFuncSetAttribute(bf_gemm<0>, cudaFuncAttributeMaxDynamicSharedMemorySize, SMEM_G);
    cudaFuncSetAttribute(bf_gemm<1>, cudaFuncAttributeMaxDynamicSharedMemorySize, SMEM_G);
    cudaFuncSetAttribute(bf_gemm<2>, cudaFuncAttributeMaxDynamicSharedMemorySize, SMEM_G);

    // 0) weights -> bf16
    cvt_w<<<(3 * DI * DMD + 255) / 256, 256>>>(W_in, W_dt, W_out);

    // 1) LayerNorm -> bf16
    ln_kernel<<<MTOK, DMD>>>(x, gamma, beta, xn);

    // 2) GEMM1: [silu(x_proj)|silu(z)] fp32 -> g_xz ; raw dt_in bf16 -> g_dtin
    bf_gemm<0><<<dim3(9, MTOK / 128), 512, SMEM_G>>>(
        xn, DMD, win, DMD, b_in, xz, 2 * DI, dtin, DMD, nullptr);

    // 3) GEMM2: dt = softplus(dt_in @ W_dt^T + b_dt)
    bf_gemm<1><<<dim3(3, MTOK / 128), 512, SMEM_G>>>(
        dtin, DI, wdt, DI, b_dt, dtb, DI, nullptr, DI, nullptr);

    // 4) chunked scan + gating -> y (bf16)
    scan_kernel<<<NCHUNK, DI>>>(xz, dtb, A_log, D_vec, yb);

    // 5) GEMM3: out = y @ W_out^T + b_out + residual
    bf_gemm<2><<<dim3(2, MTOK / 128), 512, SMEM_G>>>(
        yb, DI, wout, DI, b_out, out, DMD, nullptr, DI, x);
}